// round 10
// baseline (speedup 1.0000x reference)
#include <cuda_runtime.h>
#include <math.h>
#include <stdint.h>

#define B_    64
#define NR_   16384
#define IC_   16
#define NC_   10
#define OC_   16
#define CO_   160
#define NS_   16          // K splits (grid.x)
#define KB_   1024        // K per CTA
#define KT_   32          // K per stage
#define NT_   (KB_/KT_)   // 32 stages
#define PITCH_A 20        // u32 per A smem row (16 pairs + 4 pad)
#define PITCH_W 40        // floats per W smem row (32 + 8 pad)
#define NPAIR   (NR_/2)   // 8192 bf16x2 pairs per (i,b)
#define STG_FLOATS (64*PITCH_A + 64*PITCH_A + CO_*PITCH_W)   // 8960
#define SMEM_GEMM  (3 * STG_FLOATS * 4)                      // 107520 B
#define SMEM_ROUT  ((IC_*B_*OC_ + B_*OC_ + 48) * 4)

// ---------------- device scratch ----------------
__device__ uint32_t g_xh[(size_t)IC_*B_*NPAIR];     // x hi bf16x2 [i][b][rpair]
__device__ uint32_t g_xl[(size_t)IC_*B_*NPAIR];     // x lo bf16x2
__device__ float g_upart[(size_t)IC_*NS_*B_*CO_];   // partials [i][split][b][co]
__device__ float g_v[B_*CO_];

// ---------------- helpers ----------------
__device__ __forceinline__ uint32_t smem_u32(const void* p) {
    uint32_t a;
    asm("{ .reg .u64 t; cvta.to.shared.u64 t, %1; cvt.u32.u64 %0, t; }" : "=r"(a) : "l"(p));
    return a;
}
__device__ __forceinline__ void cp16(uint32_t saddr, const void* g) {
    asm volatile("cp.async.cg.shared.global [%0], [%1], 16;" :: "r"(saddr), "l"(g));
}
#define CP_COMMIT() asm volatile("cp.async.commit_group;" ::: "memory")

// split packed pair (f0=k even, f1=k odd) into bf16x2 hi + bf16x2 lo
__device__ __forceinline__ void split_bf16x2(float f0, float f1, uint32_t& h, uint32_t& l) {
    asm("cvt.rn.satfinite.bf16x2.f32 %0, %1, %2;" : "=r"(h) : "f"(f1), "f"(f0));
    float g0 = __uint_as_float(h << 16);
    float g1 = __uint_as_float(h & 0xFFFF0000u);
    asm("cvt.rn.satfinite.bf16x2.f32 %0, %1, %2;" : "=r"(l) : "f"(f1 - g1), "f"(f0 - g0));
}
__device__ __forceinline__ void mma_bf16(float* d, const uint32_t* a,
                                         uint32_t b0, uint32_t b1) {
    asm("mma.sync.aligned.m16n8k16.row.col.f32.bf16.bf16.f32 "
        "{%0,%1,%2,%3},{%4,%5,%6,%7},{%8,%9},{%0,%1,%2,%3};"
        : "+f"(d[0]), "+f"(d[1]), "+f"(d[2]), "+f"(d[3])
        : "r"(a[0]), "r"(a[1]), "r"(a[2]), "r"(a[3]), "r"(b0), "r"(b1));
}

// ---------------- kernel 1: transpose+split x[b,r,i] -> xh/xl[i][b][rpair] ----
#define TP 132   // smem row pitch (floats): 16B-aligned rows, phase2 LDS.128
__global__ __launch_bounds__(256) void transpose_kernel(const float* __restrict__ x) {
    __shared__ float s[4 * 16 * TP];            // [b4*16+i][r128]
    const int tid = threadIdx.x;
    const int r0 = blockIdx.x * 128, b0 = blockIdx.y * 4;
    #pragma unroll
    for (int it = 0; it < 8; it++) {
        int idx = it * 256 + tid;               // 2048 float4 over i
        int iq = idx & 3, r = (idx >> 2) & 127, b = idx >> 9;
        float4 v = *(const float4*)(x + ((size_t)(b0 + b) * NR_ + (r0 + r)) * IC_ + iq * 4);
        int base = (b * 16 + iq * 4) * TP + r;
        s[base] = v.x; s[base + TP] = v.y; s[base + 2 * TP] = v.z; s[base + 3 * TP] = v.w;
    }
    __syncthreads();
    #pragma unroll
    for (int it = 0; it < 4; it++) {
        int idx = it * 256 + tid;               // 1024 tasks: 8 r each
        int rg = idx & 15, i = (idx >> 4) & 15, b = idx >> 8;
        const float4* row = (const float4*)&s[(b * 16 + i) * TP + rg * 8];
        float4 f0 = row[0];                     // r = rg*8 .. +3
        float4 f1 = row[1];                     // r = rg*8+4 .. +7
        uint4 h, l;
        split_bf16x2(f0.x, f0.y, h.x, l.x);
        split_bf16x2(f0.z, f0.w, h.y, l.y);
        split_bf16x2(f1.x, f1.y, h.z, l.z);
        split_bf16x2(f1.z, f1.w, h.w, l.w);
        size_t po = (size_t)(i * B_ + b0 + b) * NPAIR + (r0 >> 1) + rg * 4;
        *(uint4*)(g_xh + po) = h;
        *(uint4*)(g_xl + po) = l;
    }
}

// ---------------- kernel 2: mma.sync bf16x3 K-split GEMM ----------------
extern __shared__ float smf[];

__global__ __launch_bounds__(256, 2) void gemm_kernel(const float* __restrict__ W) {
    const int split = blockIdx.x, i = blockIdx.y;
    const int tid = threadIdx.x;
    const int wid = tid >> 5, lane = tid & 31;
    const int g = lane >> 2, c = lane & 3;
    const int mt = wid & 1;                     // m-tile (32 b rows)
    const int ng = wid >> 1;                    // n-group (40 co)
    const float* Wb = W + (size_t)i * CO_ * NR_ + split * KB_;
    const size_t ib = (size_t)i * B_;

    float acc[2][5][4];
    #pragma unroll
    for (int t = 0; t < 2; t++)
        #pragma unroll
        for (int nt = 0; nt < 5; nt++)
            #pragma unroll
            for (int q = 0; q < 4; q++) acc[t][nt][q] = 0.f;

    auto load_stage = [&](int t) {
        uint32_t sbase = smem_u32(smf + (t % 3) * STG_FLOATS);
        const int p0 = split * (KB_ / 2) + t * (KT_ / 2);   // pair offset
        #pragma unroll
        for (int j = 0; j < 7; j++) {           // 1792 chunks of 16B
            int idx = tid + j * 256;
            if (idx < 512) {
                int half = idx >> 8, r2 = idx & 255;
                int row = r2 >> 2, ch = r2 & 3;
                const uint32_t* src = (half ? g_xl : g_xh) + (ib + row) * NPAIR + p0 + ch * 4;
                cp16(sbase + (half * 1280 + row * PITCH_A + ch * 4) * 4, src);
            } else {
                int idx2 = idx - 512;
                int row = idx2 >> 3, ch = idx2 & 7;
                cp16(sbase + (2560 + row * PITCH_W + ch * 4) * 4,
                     Wb + (size_t)row * NR_ + t * KT_ + ch * 4);
            }
        }
        CP_COMMIT();
    };

    load_stage(0); load_stage(1); load_stage(2);

    for (int t = 0; t < NT_; t++) {
        if (t < NT_ - 2)       asm volatile("cp.async.wait_group 2;" ::: "memory");
        else if (t == NT_ - 2) asm volatile("cp.async.wait_group 1;" ::: "memory");
        else                   asm volatile("cp.async.wait_group 0;" ::: "memory");
        __syncthreads();
        const uint32_t* xh = (const uint32_t*)(smf + (t % 3) * STG_FLOATS);
        const uint32_t* xl = xh + 1280;
        const float*    ws = (const float*)(xh + 2560);
        #pragma unroll
        for (int kk = 0; kk < 2; kk++) {
            uint32_t ah[2][4], al[2][4];
            #pragma unroll
            for (int st2 = 0; st2 < 2; st2++) {
                const int rb = mt * 32 + st2 * 16;
                const int cA = kk * 8 + c;
                ah[st2][0] = xh[(rb + g)     * PITCH_A + cA];
                ah[st2][1] = xh[(rb + g + 8) * PITCH_A + cA];
                ah[st2][2] = xh[(rb + g)     * PITCH_A + cA + 4];
                ah[st2][3] = xh[(rb + g + 8) * PITCH_A + cA + 4];
                al[st2][0] = xl[(rb + g)     * PITCH_A + cA];
                al[st2][1] = xl[(rb + g + 8) * PITCH_A + cA];
                al[st2][2] = xl[(rb + g)     * PITCH_A + cA + 4];
                al[st2][3] = xl[(rb + g + 8) * PITCH_A + cA + 4];
            }
            const int kc = kk * 16;
            #pragma unroll
            for (int nt = 0; nt < 5; nt++) {
                const int n = ng * 40 + nt * 8 + g;
                float2 q0 = *(const float2*)&ws[n * PITCH_W + kc + 2 * c];
                float2 q1 = *(const float2*)&ws[n * PITCH_W + kc + 2 * c + 8];
                uint32_t bh0, bl0, bh1, bl1;
                split_bf16x2(q0.x, q0.y, bh0, bl0);
                split_bf16x2(q1.x, q1.y, bh1, bl1);
                #pragma unroll
                for (int st2 = 0; st2 < 2; st2++) {
                    mma_bf16(acc[st2][nt], ah[st2], bh0, bh1);   // hi*hi
                    mma_bf16(acc[st2][nt], ah[st2], bl0, bl1);   // hi*lo
                    mma_bf16(acc[st2][nt], al[st2], bh0, bh1);   // lo*hi
                }
            }
        }
        __syncthreads();
        if (t + 3 < NT_) load_stage(t + 3);
    }

    // epilogue -> g_upart[i][split][b][co]
    float* outp = g_upart + (size_t)(i * NS_ + split) * B_ * CO_;
    #pragma unroll
    for (int st2 = 0; st2 < 2; st2++) {
        const int row = mt * 32 + st2 * 16 + g;
        #pragma unroll
        for (int nt = 0; nt < 5; nt++) {
            const int col = ng * 40 + nt * 8 + 2 * c;
            *(float2*)(outp + (size_t)row * CO_ + col)       = make_float2(acc[st2][nt][0], acc[st2][nt][1]);
            *(float2*)(outp + (size_t)(row + 8) * CO_ + col) = make_float2(acc[st2][nt][2], acc[st2][nt][3]);
        }
    }
}

// ---------------- kernel 3: fused reduce + routing (one CTA per column c) ----
extern __shared__ float rsm[];
__global__ __launch_bounds__(1024) void routing_kernel(float* __restrict__ out) {
    const int c = blockIdx.x;
    const int tid = threadIdx.x;
    float* su = rsm;                       // [i][b*o] 16x1024
    float* sv = rsm + IC_ * 1024;          // [b*o] 1024
    float* sb = sv + 1024;                 // bij col (16)
    float* sc = sb + IC_;                  // softmax  (16)

    // ---- reduce splits directly: su[i][b][o] = sum_sp upart[i][sp][b][c*16+o]
    {
        const int i4 = tid >> 8;           // 0..3
        const int rem = tid & 255;         // b*4 + oq
        const int b = rem >> 2, oq = rem & 3;
        #pragma unroll
        for (int w = 0; w < 4; w++) {
            const int i = i4 + w * 4;
            const float* p = g_upart + ((size_t)(i * NS_) * B_ + b) * CO_ + c * OC_ + oq * 4;
            float4 s = make_float4(0.f, 0.f, 0.f, 0.f);
            #pragma unroll
            for (int sp = 0; sp < NS_; sp++) {
                float4 v = *(const float4*)(p + (size_t)sp * B_ * CO_);
                s.x += v.x; s.y += v.y; s.z += v.z; s.w += v.w;
            }
            *(float4*)(su + i * 1024 + b * OC_ + oq * 4) = s;
        }
    }
    if (tid < IC_) sb[tid] = 0.f;
    __syncthreads();

    for (int it = 0; it < 3; it++) {
        if (tid < 32) {                    // softmax over i: lane j owns i=j (j<16)
            float bj = (tid < IC_) ? sb[tid] : -1e30f;
            float m = bj;
            #pragma unroll
            for (int off = 8; off > 0; off >>= 1)
                m = fmaxf(m, __shfl_xor_sync(0xFFFFFFFF, m, off, 16));
            float e = (tid < IC_) ? expf(bj - m) : 0.f;
            float sum = e;
            #pragma unroll
            for (int off = 8; off > 0; off >>= 1)
                sum += __shfl_xor_sync(0xFFFFFFFF, sum, off, 16);
            if (tid < IC_) sc[tid] = e / sum;
        }
        __syncthreads();
        {                                  // s_j + squash, one element/thread
            float s = 0.f;
            #pragma unroll
            for (int i = 0; i < IC_; i++) s += sc[i] * su[i * 1024 + tid];
            sv[tid] = s * fabsf(s) / (1.f + s * s);
        }
        __syncthreads();
        if (it < 2) {                      // agreement: warp w handles i=w (w<16)
            int i = tid >> 5, lane = tid & 31;
            if (i < IC_) {
                float p = 0.f;
                #pragma unroll
                for (int j = 0; j < 32; j++) {
                    int e = lane + j * 32;
                    p += su[i * 1024 + e] * sv[e];
                }
                #pragma unroll
                for (int off = 16; off > 0; off >>= 1)
                    p += __shfl_xor_sync(0xFFFFFFFF, p, off);
                if (lane == 0) sb[i] += p * (1.f / B_);
            }
            __syncthreads();
        }
    }
    // write v slice to output tensor and to g_v for the FC head
    int b = tid >> 4, o = tid & 15;
    float v = sv[tid];
    out[B_ + b * CO_ + c * OC_ + o] = v;
    g_v[b * CO_ + c * OC_ + o] = v;
}

// ---------------- kernel 4: FC + sigmoid (pred only) ----------------
__global__ __launch_bounds__(1024) void final_kernel(const float* __restrict__ fc_w,
                                                     const float* __restrict__ fc_b,
                                                     float* __restrict__ out) {
    int tid = threadIdx.x;
    int b = tid >> 4, j = tid & 15;
    float p = 0.f;
    #pragma unroll
    for (int q = 0; q < 10; q++) {
        int co = j + q * 16;
        p += g_v[b * CO_ + co] * fc_w[co];
    }
    #pragma unroll
    for (int off = 8; off > 0; off >>= 1)
        p += __shfl_xor_sync(0xFFFFFFFF, p, off, 16);
    if (j == 0) out[b] = 1.f / (1.f + expf(-(p + fc_b[0])));
}

// ---------------- launcher ----------------
extern "C" void kernel_launch(void* const* d_in, const int* in_sizes, int n_in,
                              void* d_out, int out_size) {
    const float* x    = (const float*)d_in[0];
    const float* W    = (const float*)d_in[1];
    const float* fc_w = (const float*)d_in[2];
    const float* fc_b = (const float*)d_in[3];
    float* out = (float*)d_out;

    static int attr_done = 0;
    if (!attr_done) {
        cudaFuncSetAttribute(gemm_kernel, cudaFuncAttributeMaxDynamicSharedMemorySize, SMEM_GEMM);
        cudaFuncSetAttribute(routing_kernel, cudaFuncAttributeMaxDynamicSharedMemorySize, SMEM_ROUT);
        attr_done = 1;
    }

    transpose_kernel<<<dim3(NR_ / 128, B_ / 4), 256>>>(x);
    gemm_kernel<<<dim3(NS_, IC_), 256, SMEM_GEMM>>>(W);
    routing_kernel<<<NC_, 1024, SMEM_ROUT>>>(out);
    final_kernel<<<1, 1024>>>(fc_w, fc_b, out);
}

// round 11
// speedup vs baseline: 1.0625x; 1.0625x over previous
#include <cuda_runtime.h>
#include <math.h>
#include <stdint.h>

#define B_    64
#define NR_   16384
#define IC_   16
#define NC_   10
#define OC_   16
#define CO_   160
#define NS_   16          // K splits (grid.x)
#define KB_   1024        // K per CTA
#define KT_   32          // K per stage
#define NT_   (KB_/KT_)   // 32 stages
#define PITCH_A 20        // u32 per A smem row (16 pairs + 4 pad)
#define PITCH_W 40        // floats per W smem row (32 + 8 pad)
#define NPAIR   (NR_/2)   // 8192 bf16x2 pairs per (i,b)
#define STG_FLOATS (64*PITCH_A + 64*PITCH_A + CO_*PITCH_W)   // 8960
#define SMEM_GEMM  (3 * STG_FLOATS * 4)                      // 107520 B
#define SMEM_ROUT  ((IC_*B_*OC_ + B_*OC_ + 48) * 4)

// ---------------- device scratch ----------------
__device__ uint32_t g_xh[(size_t)IC_*B_*NPAIR];     // x hi bf16x2 [i][b][rpair]
__device__ uint32_t g_xl[(size_t)IC_*B_*NPAIR];     // x lo bf16x2
__device__ float g_upart[(size_t)IC_*NS_*B_*CO_];   // partials [i][split][b][co]
__device__ float g_uhatC[NC_*IC_*B_*OC_];           // uhat [c][i][b][o]
__device__ float g_fcp[NC_*B_];                     // per-c FC partials
__device__ int g_bar;

// ---------------- helpers ----------------
__device__ __forceinline__ uint32_t smem_u32(const void* p) {
    uint32_t a;
    asm("{ .reg .u64 t; cvta.to.shared.u64 t, %1; cvt.u32.u64 %0, t; }" : "=r"(a) : "l"(p));
    return a;
}
__device__ __forceinline__ void cp16(uint32_t saddr, const void* g) {
    asm volatile("cp.async.cg.shared.global [%0], [%1], 16;" :: "r"(saddr), "l"(g));
}
#define CP_COMMIT() asm volatile("cp.async.commit_group;" ::: "memory")

// split packed pair (f0=k even, f1=k odd) into bf16x2 hi + bf16x2 lo
__device__ __forceinline__ void split_bf16x2(float f0, float f1, uint32_t& h, uint32_t& l) {
    asm("cvt.rn.satfinite.bf16x2.f32 %0, %1, %2;" : "=r"(h) : "f"(f1), "f"(f0));
    float g0 = __uint_as_float(h << 16);
    float g1 = __uint_as_float(h & 0xFFFF0000u);
    asm("cvt.rn.satfinite.bf16x2.f32 %0, %1, %2;" : "=r"(l) : "f"(f1 - g1), "f"(f0 - g0));
}
__device__ __forceinline__ void mma_bf16(float* d, const uint32_t* a,
                                         uint32_t b0, uint32_t b1) {
    asm("mma.sync.aligned.m16n8k16.row.col.f32.bf16.bf16.f32 "
        "{%0,%1,%2,%3},{%4,%5,%6,%7},{%8,%9},{%0,%1,%2,%3};"
        : "+f"(d[0]), "+f"(d[1]), "+f"(d[2]), "+f"(d[3])
        : "r"(a[0]), "r"(a[1]), "r"(a[2]), "r"(a[3]), "r"(b0), "r"(b1));
}

// ---------------- kernel 1: transpose+split x[b,r,i] -> xh/xl[i][b][rpair] ----
#define TP 132   // smem row pitch (floats): 16B-aligned rows, phase2 LDS.128
__global__ __launch_bounds__(256) void transpose_kernel(const float* __restrict__ x) {
    __shared__ float s[4 * 16 * TP];            // [b4*16+i][r128]
    const int tid = threadIdx.x;
    const int r0 = blockIdx.x * 128, b0 = blockIdx.y * 4;
    if (blockIdx.x == 0 && blockIdx.y == 0 && tid == 0) g_bar = 0;
    #pragma unroll
    for (int it = 0; it < 8; it++) {
        int idx = it * 256 + tid;               // 2048 float4 over i
        int iq = idx & 3, r = (idx >> 2) & 127, b = idx >> 9;
        float4 v = *(const float4*)(x + ((size_t)(b0 + b) * NR_ + (r0 + r)) * IC_ + iq * 4);
        int base = (b * 16 + iq * 4) * TP + r;
        s[base] = v.x; s[base + TP] = v.y; s[base + 2 * TP] = v.z; s[base + 3 * TP] = v.w;
    }
    __syncthreads();
    #pragma unroll
    for (int it = 0; it < 4; it++) {
        int idx = it * 256 + tid;               // 1024 tasks: 8 r each
        int rg = idx & 15, i = (idx >> 4) & 15, b = idx >> 8;
        const float4* row = (const float4*)&s[(b * 16 + i) * TP + rg * 8];
        float4 f0 = row[0];                     // r = rg*8 .. +3
        float4 f1 = row[1];                     // r = rg*8+4 .. +7
        uint4 h, l;
        split_bf16x2(f0.x, f0.y, h.x, l.x);
        split_bf16x2(f0.z, f0.w, h.y, l.y);
        split_bf16x2(f1.x, f1.y, h.z, l.z);
        split_bf16x2(f1.z, f1.w, h.w, l.w);
        size_t po = (size_t)(i * B_ + b0 + b) * NPAIR + (r0 >> 1) + rg * 4;
        *(uint4*)(g_xh + po) = h;
        *(uint4*)(g_xl + po) = l;
    }
}

// ---------------- kernel 2: mma.sync bf16x3 K-split GEMM ----------------
extern __shared__ float smf[];

__global__ __launch_bounds__(256, 2) void gemm_kernel(const float* __restrict__ W) {
    const int split = blockIdx.x, i = blockIdx.y;
    const int tid = threadIdx.x;
    const int wid = tid >> 5, lane = tid & 31;
    const int g = lane >> 2, c = lane & 3;
    const int mt = wid & 1;                     // m-tile (32 b rows)
    const int ng = wid >> 1;                    // n-group (40 co)
    const float* Wb = W + (size_t)i * CO_ * NR_ + split * KB_;
    const size_t ib = (size_t)i * B_;

    float acc[2][5][4];
    #pragma unroll
    for (int t = 0; t < 2; t++)
        #pragma unroll
        for (int nt = 0; nt < 5; nt++)
            #pragma unroll
            for (int q = 0; q < 4; q++) acc[t][nt][q] = 0.f;

    auto load_stage = [&](int t) {
        uint32_t sbase = smem_u32(smf + (t % 3) * STG_FLOATS);
        const int p0 = split * (KB_ / 2) + t * (KT_ / 2);   // pair offset
        #pragma unroll
        for (int j = 0; j < 7; j++) {           // 1792 chunks of 16B
            int idx = tid + j * 256;
            if (idx < 512) {
                int half = idx >> 8, r2 = idx & 255;
                int row = r2 >> 2, ch = r2 & 3;
                const uint32_t* src = (half ? g_xl : g_xh) + (ib + row) * NPAIR + p0 + ch * 4;
                cp16(sbase + (half * 1280 + row * PITCH_A + ch * 4) * 4, src);
            } else {
                int idx2 = idx - 512;
                int row = idx2 >> 3, ch = idx2 & 7;
                cp16(sbase + (2560 + row * PITCH_W + ch * 4) * 4,
                     Wb + (size_t)row * NR_ + t * KT_ + ch * 4);
            }
        }
        CP_COMMIT();
    };

    load_stage(0); load_stage(1); load_stage(2);

    for (int t = 0; t < NT_; t++) {
        if (t < NT_ - 2)       asm volatile("cp.async.wait_group 2;" ::: "memory");
        else if (t == NT_ - 2) asm volatile("cp.async.wait_group 1;" ::: "memory");
        else                   asm volatile("cp.async.wait_group 0;" ::: "memory");
        __syncthreads();
        const uint32_t* xh = (const uint32_t*)(smf + (t % 3) * STG_FLOATS);
        const uint32_t* xl = xh + 1280;
        const float*    ws = (const float*)(xh + 2560);
        #pragma unroll
        for (int kk = 0; kk < 2; kk++) {
            uint32_t ah[2][4], al[2][4];
            #pragma unroll
            for (int st2 = 0; st2 < 2; st2++) {
                const int rb = mt * 32 + st2 * 16;
                const int cA = kk * 8 + c;
                ah[st2][0] = xh[(rb + g)     * PITCH_A + cA];
                ah[st2][1] = xh[(rb + g + 8) * PITCH_A + cA];
                ah[st2][2] = xh[(rb + g)     * PITCH_A + cA + 4];
                ah[st2][3] = xh[(rb + g + 8) * PITCH_A + cA + 4];
                al[st2][0] = xl[(rb + g)     * PITCH_A + cA];
                al[st2][1] = xl[(rb + g + 8) * PITCH_A + cA];
                al[st2][2] = xl[(rb + g)     * PITCH_A + cA + 4];
                al[st2][3] = xl[(rb + g + 8) * PITCH_A + cA + 4];
            }
            const int kc = kk * 16;
            #pragma unroll
            for (int nt = 0; nt < 5; nt++) {
                const int n = ng * 40 + nt * 8 + g;
                float2 q0 = *(const float2*)&ws[n * PITCH_W + kc + 2 * c];
                float2 q1 = *(const float2*)&ws[n * PITCH_W + kc + 2 * c + 8];
                uint32_t bh0, bl0, bh1, bl1;
                split_bf16x2(q0.x, q0.y, bh0, bl0);
                split_bf16x2(q1.x, q1.y, bh1, bl1);
                #pragma unroll
                for (int st2 = 0; st2 < 2; st2++) {
                    mma_bf16(acc[st2][nt], ah[st2], bh0, bh1);   // hi*hi
                    mma_bf16(acc[st2][nt], ah[st2], bl0, bl1);   // hi*lo
                    mma_bf16(acc[st2][nt], al[st2], bh0, bh1);   // lo*hi
                }
            }
        }
        __syncthreads();
        if (t + 3 < NT_) load_stage(t + 3);
    }

    // epilogue -> g_upart[i][split][b][co]
    float* outp = g_upart + (size_t)(i * NS_ + split) * B_ * CO_;
    #pragma unroll
    for (int st2 = 0; st2 < 2; st2++) {
        const int row = mt * 32 + st2 * 16 + g;
        #pragma unroll
        for (int nt = 0; nt < 5; nt++) {
            const int col = ng * 40 + nt * 8 + 2 * c;
            *(float2*)(outp + (size_t)row * CO_ + col)       = make_float2(acc[st2][nt][0], acc[st2][nt][1]);
            *(float2*)(outp + (size_t)(row + 8) * CO_ + col) = make_float2(acc[st2][nt][2], acc[st2][nt][3]);
        }
    }
}

// ---------------- kernel 3: reduce splits -> uhat[c][i][b][o] ----------------
__global__ void reduce_kernel() {
    int gid = blockIdx.x * 256 + threadIdx.x;   // 40960 float4
    int oq = gid & 3, b = (gid >> 2) & 63, i = (gid >> 8) & 15, c = gid >> 12;
    const float* p = g_upart + ((size_t)(i * NS_) * B_ + b) * CO_ + c * OC_ + oq * 4;
    float4 s = make_float4(0.f, 0.f, 0.f, 0.f);
    #pragma unroll
    for (int sp = 0; sp < NS_; sp++) {
        float4 v = *(const float4*)(p + (size_t)sp * B_ * CO_);
        s.x += v.x; s.y += v.y; s.z += v.z; s.w += v.w;
    }
    ((float4*)g_uhatC)[gid] = s;
}

// ---------------- kernel 4: routing + FC head (one CTA per column c) -------
extern __shared__ float rsm[];
__global__ __launch_bounds__(1024) void routing_kernel(const float* __restrict__ fc_w,
                                                       const float* __restrict__ fc_b,
                                                       float* __restrict__ out) {
    const int c = blockIdx.x;
    const int tid = threadIdx.x;
    float* su = rsm;                       // [i][b*o] 16x1024
    float* sv = rsm + IC_ * 1024;          // [b*o] 1024
    float* sb = sv + 1024;                 // bij col (16)
    float* sc = sb + IC_;                  // softmax  (16)

    // load uhat slice for column c: contiguous 64 KB
    const float4* src = (const float4*)(g_uhatC + c * IC_ * 1024);
    #pragma unroll
    for (int j = 0; j < 4; j++)
        ((float4*)su)[tid + j * 1024] = src[tid + j * 1024];
    if (tid < IC_) sb[tid] = 0.f;
    __syncthreads();

    for (int it = 0; it < 3; it++) {
        if (tid < 32) {                    // softmax over i: lane j owns i=j (j<16)
            float bj = (tid < IC_) ? sb[tid] : -1e30f;
            float m = bj;
            #pragma unroll
            for (int off = 8; off > 0; off >>= 1)
                m = fmaxf(m, __shfl_xor_sync(0xFFFFFFFF, m, off, 16));
            float e = (tid < IC_) ? expf(bj - m) : 0.f;
            float sum = e;
            #pragma unroll
            for (int off = 8; off > 0; off >>= 1)
                sum += __shfl_xor_sync(0xFFFFFFFF, sum, off, 16);
            if (tid < IC_) sc[tid] = e / sum;
        }
        __syncthreads();
        {                                  // s_j + squash, one element/thread
            float s = 0.f;
            #pragma unroll
            for (int i = 0; i < IC_; i++) s += sc[i] * su[i * 1024 + tid];
            sv[tid] = s * fabsf(s) / (1.f + s * s);
        }
        __syncthreads();
        if (it < 2) {                      // agreement: warp w handles i=w (w<16)
            int i = tid >> 5, lane = tid & 31;
            if (i < IC_) {
                float p = 0.f;
                #pragma unroll
                for (int j = 0; j < 32; j++) {
                    int e = lane + j * 32;
                    p += su[i * 1024 + e] * sv[e];
                }
                #pragma unroll
                for (int off = 16; off > 0; off >>= 1)
                    p += __shfl_xor_sync(0xFFFFFFFF, p, off);
                if (lane == 0) sb[i] += p * (1.f / B_);
            }
            __syncthreads();
        }
    }
    // write v slice + per-c FC partial
    int b = tid >> 4, o = tid & 15;
    float v = sv[tid];
    out[B_ + b * CO_ + c * OC_ + o] = v;
    float p = v * fc_w[c * OC_ + o];
    #pragma unroll
    for (int off = 8; off > 0; off >>= 1)
        p += __shfl_xor_sync(0xFFFFFFFF, p, off, 16);
    if (o == 0) g_fcp[c * B_ + b] = p;

    // FC head: CTA 0 waits for all 10 CTAs (all co-resident at grid=10)
    __threadfence();
    __syncthreads();
    if (tid == 0) atomicAdd(&g_bar, 1);
    if (c != 0) return;
    if (tid == 0) while (atomicAdd(&g_bar, 0) < NC_) __nanosleep(64);
    __syncthreads();
    __threadfence();
    if (tid < B_) {
        float a = fc_b[0];
        #pragma unroll
        for (int cc = 0; cc < NC_; cc++) a += g_fcp[cc * B_ + tid];
        out[tid] = 1.f / (1.f + expf(-a));
    }
}

// ---------------- launcher ----------------
extern "C" void kernel_launch(void* const* d_in, const int* in_sizes, int n_in,
                              void* d_out, int out_size) {
    const float* x    = (const float*)d_in[0];
    const float* W    = (const float*)d_in[1];
    const float* fc_w = (const float*)d_in[2];
    const float* fc_b = (const float*)d_in[3];
    float* out = (float*)d_out;

    static int attr_done = 0;
    if (!attr_done) {
        cudaFuncSetAttribute(gemm_kernel, cudaFuncAttributeMaxDynamicSharedMemorySize, SMEM_GEMM);
        cudaFuncSetAttribute(routing_kernel, cudaFuncAttributeMaxDynamicSharedMemorySize, SMEM_ROUT);
        attr_done = 1;
    }

    transpose_kernel<<<dim3(NR_ / 128, B_ / 4), 256>>>(x);
    gemm_kernel<<<dim3(NS_, IC_), 256, SMEM_GEMM>>>(W);
    reduce_kernel<<<160, 256>>>();
    routing_kernel<<<NC_, 1024, SMEM_ROUT>>>(fc_w, fc_b, out);
}